// round 15
// baseline (speedup 1.0000x reference)
#include <cuda_runtime.h>
#include <cuda_bf16.h>
#include <math.h>
#include <stdint.h>

#define BB_ 2
#define S_  2048
#define D_  1024
#define H_  16
#define HD_ 64
#define M_  (BB_*S_)     // 4096
#define KTOT (2*D_)      // 2048 (hi|lo concatenated K)

// ---------------------------------------------------------------------------
// Scratch (device globals; no allocation allowed)
// ---------------------------------------------------------------------------
__device__ float g_y[M_*D_];
__device__ __nv_bfloat16 g_xc[M_*KTOT];       // x  hi|lo concat along K
__device__ __nv_bfloat16 g_wqc[D_*KTOT];
__device__ __nv_bfloat16 g_wkc[D_*KTOT];
__device__ __nv_bfloat16 g_wvc[D_*KTOT];
__device__ __nv_bfloat16 g_woc[D_*KTOT];
__device__ __nv_bfloat16 g_attnc[M_*KTOT];    // attention out hi|lo concat
__device__ __nv_bfloat16 g_qc[BB_*H_*S_*64];  // per-head Q bf16 (hi only)
__device__ __nv_bfloat16 g_kc[BB_*H_*S_*64];  // per-head K bf16 (hi only)
__device__ __nv_bfloat16 g_vc[BB_*H_*S_*128]; // per-head V bf16 [hi64|lo64]
__device__ float g_cos[S_*HD_];
__device__ float g_sin[S_*HD_];

// ---------------------------------------------------------------------------
// Helpers
// ---------------------------------------------------------------------------
__device__ __forceinline__ uint32_t smem_u32(const void* p) {
    uint32_t a;
    asm("{ .reg .u64 t; cvta.to.shared.u64 t, %1; cvt.u32.u64 %0, t; }" : "=r"(a) : "l"(p));
    return a;
}
__device__ __forceinline__ void cp16(uint32_t s, const void* g) {
    asm volatile("cp.async.cg.shared.global [%0], [%1], 16;" :: "r"(s), "l"(g));
}
__device__ __forceinline__ void ldsm4(uint32_t* r, uint32_t a) {
    asm volatile("ldmatrix.sync.aligned.m8n8.x4.shared.b16 {%0,%1,%2,%3}, [%4];"
                 : "=r"(r[0]), "=r"(r[1]), "=r"(r[2]), "=r"(r[3]) : "r"(a));
}
__device__ __forceinline__ void ldsm4t(uint32_t* r, uint32_t a) {
    asm volatile("ldmatrix.sync.aligned.m8n8.x4.trans.shared.b16 {%0,%1,%2,%3}, [%4];"
                 : "=r"(r[0]), "=r"(r[1]), "=r"(r[2]), "=r"(r[3]) : "r"(a));
}
__device__ __forceinline__ void ldsm2(uint32_t* r, uint32_t a) {
    asm volatile("ldmatrix.sync.aligned.m8n8.x2.shared.b16 {%0,%1}, [%2];"
                 : "=r"(r[0]), "=r"(r[1]) : "r"(a));
}
__device__ __forceinline__ void mma16816(float* c, const uint32_t* a, const uint32_t* b) {
    asm volatile("mma.sync.aligned.m16n8k16.row.col.f32.bf16.bf16.f32 "
                 "{%0,%1,%2,%3}, {%4,%5,%6,%7}, {%8,%9}, {%0,%1,%2,%3};"
                 : "+f"(c[0]), "+f"(c[1]), "+f"(c[2]), "+f"(c[3])
                 : "r"(a[0]), "r"(a[1]), "r"(a[2]), "r"(a[3]), "r"(b[0]), "r"(b[1]));
}
#define CP_COMMIT() asm volatile("cp.async.commit_group;" ::: "memory")
#define CP_WAIT(n)  asm volatile("cp.async.wait_group %0;" :: "n"(n) : "memory")

// pack two fp32 into bf16x2 hi (rounded) and lo (residual) words
__device__ __forceinline__ void split2(float v0, float v1, uint32_t& hi, uint32_t& lo) {
    __nv_bfloat16 h0 = __float2bfloat16(v0), h1 = __float2bfloat16(v1);
    float l0 = v0 - __bfloat162float(h0), l1 = v1 - __bfloat162float(h1);
    __nv_bfloat162 hp(h0, h1);
    __nv_bfloat162 lp(__float2bfloat16(l0), __float2bfloat16(l1));
    hi = *reinterpret_cast<uint32_t*>(&hp);
    lo = *reinterpret_cast<uint32_t*>(&lp);
}
__device__ __forceinline__ uint32_t packbf(float v0, float v1) {
    __nv_bfloat162 hp(__float2bfloat16(v0), __float2bfloat16(v1));
    return *reinterpret_cast<uint32_t*>(&hp);
}

// ---------------------------------------------------------------------------
// K0a: fp32 [R][1024] -> bf16 hi|lo concat [R][2048]; 5 tensors in one launch
// grid (4096, 5): y=0 -> x (4096 blocks of 1024 elems), y=1..4 -> weights
// (1024 blocks each; early-return above).
// ---------------------------------------------------------------------------
__global__ void __launch_bounds__(256) conv_kernel(
    const float* __restrict__ x, const float* __restrict__ wq,
    const float* __restrict__ wk, const float* __restrict__ wv,
    const float* __restrict__ wo,
    __nv_bfloat16* __restrict__ xc, __nv_bfloat16* __restrict__ wqc,
    __nv_bfloat16* __restrict__ wkc, __nv_bfloat16* __restrict__ wvc,
    __nv_bfloat16* __restrict__ woc)
{
    const float* src;
    __nv_bfloat16* dst;
    int z = blockIdx.y;
    if (z == 0)      { src = x;  dst = xc; }
    else if (z == 1) { src = wq; dst = wqc; if (blockIdx.x >= 1024) return; }
    else if (z == 2) { src = wk; dst = wkc; if (blockIdx.x >= 1024) return; }
    else if (z == 3) { src = wv; dst = wvc; if (blockIdx.x >= 1024) return; }
    else             { src = wo; dst = woc; if (blockIdx.x >= 1024) return; }

    size_t i = ((size_t)blockIdx.x * 256 + threadIdx.x) * 4;
    size_t r = i >> 10, c = i & 1023;
    float4 v = *(const float4*)(src + i);
    uint32_t h01, l01, h23, l23;
    split2(v.x, v.y, h01, l01);
    split2(v.z, v.w, h23, l23);
    size_t hb = r * KTOT + c;
    *(uint32_t*)(&dst[hb])            = h01;
    *(uint32_t*)(&dst[hb + 2])        = h23;
    *(uint32_t*)(&dst[hb + 1024])     = l01;
    *(uint32_t*)(&dst[hb + 1024 + 2]) = l23;
}

// ---------------------------------------------------------------------------
// K0b: RoPE sin/cos table
// ---------------------------------------------------------------------------
__global__ void rope_tab_kernel() {
    int s = blockIdx.x, hd = threadIdx.x;
    const float NLOG = 0.28782313662425574f; // ln(10000)/32
    float th = (float)s * expf(-(float)(hd & 31) * NLOG);
    float sv, cv;
    sincosf(th, &sv, &cv);
    g_cos[s * HD_ + hd] = cv;
    g_sin[s * HD_ + hd] = sv;
}

// ---------------------------------------------------------------------------
// mma.sync GEMM core: C[128,128] = A[128,2048] @ B[128,2048]^T (bf16, f32 acc)
// 3-stage cp.async pipeline, one __syncthreads per K-iteration.
// ---------------------------------------------------------------------------
#define BKg 32
#define NKIT (KTOT / BKg)  // 64
#define ASTRIDE 40
#define OPBYTES (128 * ASTRIDE * 2)   // 10240
#define GSTG (2 * OPBYTES)            // 20480 per stage (A+B)
#define GEMM_SMEM (3 * GSTG)          // 61440

__device__ __forceinline__ void gemm_loop(
    const __nv_bfloat16* __restrict__ Ab, const __nv_bfloat16* __restrict__ Bb,
    uint32_t base, float acc[4][4][4])
{
    int tid = threadIdx.x, lane = tid & 31, wid = tid >> 5;
    int wm = (wid >> 2) * 64, wn = (wid & 3) * 32;

    int r_ld = tid >> 1;
    int c_ld = (tid & 1) * 2;

    auto ldst = [&](int st, int k0) {
        uint32_t sA = base + (uint32_t)st * GSTG;
        uint32_t sB = sA + OPBYTES;
        #pragma unroll
        for (int j = 0; j < 2; j++) {
            int c = c_ld + j;
            uint32_t so = (uint32_t)(r_ld * 80 + c * 16);
            cp16(sA + so, Ab + (size_t)r_ld * KTOT + k0 + c * 8);
            cp16(sB + so, Bb + (size_t)r_ld * KTOT + k0 + c * 8);
        }
    };

    ldst(0, 0);
    CP_COMMIT();
    ldst(1, BKg);
    CP_COMMIT();

    int la = lane & 15, lka = (lane >> 4) << 3;
    int lb = lane & 7,  lkb = ((lane >> 3) & 1) << 3;

    for (int kt = 0; kt < NKIT; kt++) {
        CP_WAIT(1);
        __syncthreads();
        if (kt + 2 < NKIT) ldst((kt + 2) % 3, (kt + 2) * BKg);
        CP_COMMIT();

        int st = kt % 3;
        uint32_t aB = base + (uint32_t)st * GSTG;
        uint32_t bB = aB + OPBYTES;

        #pragma unroll
        for (int ks = 0; ks < 2; ks++) {
            int kk = ks * 16;
            uint32_t afr[4][4], bfr[4][2];
            #pragma unroll
            for (int mi = 0; mi < 4; mi++)
                ldsm4(afr[mi], aB + (uint32_t)(((wm + mi * 16 + la) * ASTRIDE + kk + lka) * 2));
            #pragma unroll
            for (int ni = 0; ni < 4; ni++)
                ldsm2(bfr[ni], bB + (uint32_t)(((wn + ni * 8 + lb) * ASTRIDE + kk + lkb) * 2));
            #pragma unroll
            for (int mi = 0; mi < 4; mi++)
                #pragma unroll
                for (int ni = 0; ni < 4; ni++)
                    mma16816(acc[mi][ni], afr[mi], bfr[ni]);
        }
    }
}

// ---------------------------------------------------------------------------
// K1: QKV projection (fused bias + RoPE), writes per-head bf16 layouts.
// grid (8, 32, 3), block 256.
// ---------------------------------------------------------------------------
__global__ void __launch_bounds__(256, 2) qkv_mma_kernel(
    const float* __restrict__ bq, const float* __restrict__ bk,
    const float* __restrict__ bv)
{
    extern __shared__ __align__(16) char gsm[];

    const __nv_bfloat16* Wc;
    const float* bias;
    __nv_bfloat16* outc;
    int dorope, isv;
    if (blockIdx.z == 0)      { Wc = g_wqc; bias = bq; outc = g_qc; dorope = 1; isv = 0; }
    else if (blockIdx.z == 1) { Wc = g_wkc; bias = bk; outc = g_kc; dorope = 1; isv = 0; }
    else                      { Wc = g_wvc; bias = bv; outc = g_vc; dorope = 0; isv = 1; }

    int m0 = blockIdx.y * 128, n0 = blockIdx.x * 128;
    float acc[4][4][4] = {};
    gemm_loop(g_xc + (size_t)m0 * KTOT, Wc + (size_t)n0 * KTOT, smem_u32(gsm), acc);

    int lane = threadIdx.x & 31, wid = threadIdx.x >> 5;
    int wm = (wid >> 2) * 64, wn = (wid & 3) * 32;

    #pragma unroll
    for (int mi = 0; mi < 4; mi++) {
        #pragma unroll
        for (int ni = 0; ni < 4; ni++) {
            int cc0 = n0 + wn + ni * 8 + (lane & 3) * 2;
            int h = cc0 >> 6, hd0 = cc0 & 63;
            float2 bi = *(const float2*)&bias[cc0];
            #pragma unroll
            for (int rr = 0; rr < 2; rr++) {
                int r = m0 + wm + mi * 16 + (lane >> 2) + rr * 8;
                int bb = r >> 11, s = r & (S_ - 1);
                float v0 = acc[mi][ni][rr * 2 + 0] + bi.x;
                float v1 = acc[mi][ni][rr * 2 + 1] + bi.y;
                if (dorope) {
                    float2 cs = *(const float2*)&g_cos[s * HD_ + hd0];
                    float2 sn = *(const float2*)&g_sin[s * HD_ + hd0];
                    float t0 = v0 * cs.x - v1 * sn.x;
                    float t1 = v1 * cs.y + v0 * sn.y;
                    v0 = t0; v1 = t1;
                }
                if (isv) {
                    uint32_t hw, lw;
                    split2(v0, v1, hw, lw);
                    size_t rowb = ((size_t)(bb * H_ + h) * S_ + s) * 128 + hd0;
                    *(uint32_t*)&outc[rowb]      = hw;
                    *(uint32_t*)&outc[rowb + 64] = lw;
                } else {
                    size_t rowb = ((size_t)(bb * H_ + h) * S_ + s) * 64 + hd0;
                    *(uint32_t*)&outc[rowb] = packbf(v0, v1);
                }
            }
        }
    }
}

// ---------------------------------------------------------------------------
// K2: attention via mma.sync bf16. grid (16 heads, 32 (b,qblk)), block 256.
// Q/K bf16 hi-only (hd 64); V hi|lo (128). 3-stage K/V pipeline, 1 sync/iter.
// Heads adjacent in blockIdx.x -> 16x L2 reuse of the mask slice.
// ---------------------------------------------------------------------------
#define QPITCH 144
#define KPITCH 144
#define VPITCH 272
#define QBYTES (128 * QPITCH)           // 18432
#define KSTG (64 * KPITCH)              // 9216
#define VSTG (64 * VPITCH)              // 17408
#define ASTG (KSTG + VSTG)              // 26624
#define ATTN_SMEM3 (QBYTES + 3 * ASTG)  // 98304

__global__ void __launch_bounds__(256, 1) attn_kernel(
    const float* __restrict__ mask, const float* __restrict__ cwp)
{
    extern __shared__ __align__(16) char smc[];
    uint32_t sb = smem_u32(smc);
    int tid = threadIdx.x, lane = tid & 31, wid = tid >> 5;
    int h = blockIdx.x;
    int b = blockIdx.y >> 4, qb = blockIdx.y & 15;
    int bh = b * H_ + h;
    int q0 = qb * 128;
    const __nv_bfloat16* Qg = g_qc + ((size_t)bh * S_ + q0) * 64;
    const __nv_bfloat16* Kg = g_kc + (size_t)bh * S_ * 64;
    const __nv_bfloat16* Vg = g_vc + (size_t)bh * S_ * 128;
    float cw = *cwp;
    const float* maskb = mask + (size_t)b * S_ * S_;

    auto stage_load = [&](int st, int kt2) {
        uint32_t kb = sb + (uint32_t)QBYTES + (uint32_t)st * ASTG;
        const __nv_bfloat16* Kp = Kg + (size_t)kt2 * 64 * 64;
        const __nv_bfloat16* Vp = Vg + (size_t)kt2 * 64 * 128;
        for (int i = tid; i < 512; i += 256) {
            int r = i >> 3, c = i & 7;
            cp16(kb + (uint32_t)(r * KPITCH + c * 16), Kp + (size_t)r * 64 + c * 8);
        }
        for (int i = tid; i < 1024; i += 256) {
            int r = i >> 4, c = i & 15;
            cp16(kb + (uint32_t)(KSTG + r * VPITCH + c * 16), Vp + (size_t)r * 128 + c * 8);
        }
    };

    // prologue: Q + stage0 in group 0; stage1 in group 1
    for (int i = tid; i < 1024; i += 256) {
        int r = i >> 3, c = i & 7;
        cp16(sb + (uint32_t)(r * QPITCH + c * 16), Qg + (size_t)r * 64 + c * 8);
    }
    stage_load(0, 0);
    CP_COMMIT();
    stage_load(1, 1);
    CP_COMMIT();

    uint32_t aQ[4][4];
    float oacc[8][4];
    #pragma unroll
    for (int n = 0; n < 8; n++)
        oacc[n][0] = oacc[n][1] = oacc[n][2] = oacc[n][3] = 0.f;
    float ls0 = 0.f, ls1 = 0.f;
    int r0q = q0 + wid * 16 + (lane >> 2);

    for (int kt = 0; kt < 32; kt++) {
        CP_WAIT(1);
        __syncthreads();
        if (kt == 0) {
            uint32_t qa = sb + (uint32_t)((wid * 16 + (lane & 15)) * QPITCH + ((lane >> 4) << 4));
            #pragma unroll
            for (int j = 0; j < 4; j++) ldsm4(aQ[j], qa + j * 32);
        }
        if (kt + 2 < 32) stage_load((kt + 2) % 3, kt + 2);
        CP_COMMIT();

        uint32_t Kb = sb + (uint32_t)QBYTES + (uint32_t)((kt % 3) * ASTG);
        uint32_t Vb = Kb + KSTG;

        // ---- QK^T over hd=64 (bf16 hi)
        float sc[8][4];
        #pragma unroll
        for (int n = 0; n < 8; n++)
            sc[n][0] = sc[n][1] = sc[n][2] = sc[n][3] = 0.f;

        uint32_t kbase = Kb + (uint32_t)((((lane & 7) + ((lane >> 4) & 1) * 8) * KPITCH)
                                         + ((lane >> 3) & 1) * 16);
        #pragma unroll
        for (int j = 0; j < 4; j++) {
            #pragma unroll
            for (int np = 0; np < 4; np++) {
                uint32_t bf[4];
                ldsm4(bf, kbase + (uint32_t)(np * (16 * KPITCH) + j * 32));
                mma16816(sc[2 * np],     aQ[j], bf);
                mma16816(sc[2 * np + 1], aQ[j], bf + 2);
            }
        }

        // ---- softmax (shift=0): p = exp(s/8 + mask*cw) -> bf16 P frags
        uint32_t Pa[8], Pb[8];
        {
            int kcol0 = kt * 64 + (lane & 3) * 2;
            const float* mrow0 = maskb + (size_t)r0q * S_ + kcol0;
            const float* mrow1 = mrow0 + 8 * S_;
            #pragma unroll
            for (int n = 0; n < 8; n++) {
                float2 m0 = *(const float2*)(mrow0 + n * 8);
                float2 m1 = *(const float2*)(mrow1 + n * 8);
                float p0 = __expf(fmaf(m0.x, cw, sc[n][0] * 0.125f));
                float p1 = __expf(fmaf(m0.y, cw, sc[n][1] * 0.125f));
                float p2 = __expf(fmaf(m1.x, cw, sc[n][2] * 0.125f));
                float p3 = __expf(fmaf(m1.y, cw, sc[n][3] * 0.125f));
                ls0 += p0 + p1; ls1 += p2 + p3;
                Pa[n] = packbf(p0, p1);
                Pb[n] = packbf(p2, p3);
            }
        }

        // ---- P @ V: [Phi|Phi] x [Vhi|Vlo], V via ldmatrix.trans
        uint32_t vbase = Vb + (uint32_t)((((lane & 7) + ((lane >> 3) & 1) * 8) * VPITCH)
                                         + ((lane >> 4) & 1) * 16);
        #pragma unroll
        for (int js = 0; js < 4; js++) {
            uint32_t aPf[4] = {Pa[2 * js], Pb[2 * js], Pa[2 * js + 1], Pb[2 * js + 1]};
            #pragma unroll
            for (int nh = 0; nh < 4; nh++) {
                uint32_t vf[4];
                ldsm4t(vf, vbase + (uint32_t)(js * (16 * VPITCH) + nh * 32));
                mma16816(oacc[2 * nh],     aPf, vf);
                mma16816(oacc[2 * nh + 1], aPf, vf + 2);
                uint32_t vl[4];
                ldsm4t(vl, vbase + (uint32_t)(js * (16 * VPITCH) + nh * 32 + 128));
                mma16816(oacc[2 * nh],     aPf, vl);
                mma16816(oacc[2 * nh + 1], aPf, vl + 2);
            }
        }
    }

    // ---- epilogue: row sums, normalize, write bf16 hi|lo concat
    ls0 += __shfl_xor_sync(0xffffffffu, ls0, 1);
    ls0 += __shfl_xor_sync(0xffffffffu, ls0, 2);
    ls1 += __shfl_xor_sync(0xffffffffu, ls1, 1);
    ls1 += __shfl_xor_sync(0xffffffffu, ls1, 2);
    float inv0 = 1.0f / ls0, inv1 = 1.0f / ls1;

    size_t row0 = (size_t)(b * S_ + r0q) * KTOT;
    size_t row1 = row0 + (size_t)8 * KTOT;
    int colh = h * 64 + (lane & 3) * 2;
    #pragma unroll
    for (int n = 0; n < 8; n++) {
        int cc = colh + n * 8;
        uint32_t h0w, l0w, h1w, l1w;
        split2(oacc[n][0] * inv0, oacc[n][1] * inv0, h0w, l0w);
        split2(oacc[n][2] * inv1, oacc[n][3] * inv1, h1w, l1w);
        *(uint32_t*)&g_attnc[row0 + cc]        = h0w;
        *(uint32_t*)&g_attnc[row0 + 1024 + cc] = l0w;
        *(uint32_t*)&g_attnc[row1 + cc]        = h1w;
        *(uint32_t*)&g_attnc[row1 + 1024 + cc] = l1w;
    }
}

// ---------------------------------------------------------------------------
// K3: output projection + bias + residual. grid (8, 32), block 256.
// ---------------------------------------------------------------------------
__global__ void __launch_bounds__(256, 2) out_mma_kernel(
    const float* __restrict__ x, const float* __restrict__ bo)
{
    extern __shared__ __align__(16) char gsm[];

    int m0 = blockIdx.y * 128, n0 = blockIdx.x * 128;
    float acc[4][4][4] = {};
    gemm_loop(g_attnc + (size_t)m0 * KTOT, g_woc + (size_t)n0 * KTOT, smem_u32(gsm), acc);

    int lane = threadIdx.x & 31, wid = threadIdx.x >> 5;
    int wm = (wid >> 2) * 64, wn = (wid & 3) * 32;

    #pragma unroll
    for (int mi = 0; mi < 4; mi++) {
        #pragma unroll
        for (int ni = 0; ni < 4; ni++) {
            int cc0 = n0 + wn + ni * 8 + (lane & 3) * 2;
            float2 bi = *(const float2*)&bo[cc0];
            #pragma unroll
            for (int rr = 0; rr < 2; rr++) {
                int r = m0 + wm + mi * 16 + (lane >> 2) + rr * 8;
                float2 xr = *(const float2*)&x[(size_t)r * D_ + cc0];
                *(float2*)&g_y[(size_t)r * D_ + cc0] =
                    make_float2(acc[mi][ni][rr * 2 + 0] + bi.x + xr.x,
                                acc[mi][ni][rr * 2 + 1] + bi.y + xr.y);
            }
        }
    }
}

// ---------------------------------------------------------------------------
// K4: LayerNorm over last dim. grid 4096, block 256.
// ---------------------------------------------------------------------------
__global__ void __launch_bounds__(256) ln_kernel(
    const float* __restrict__ gamma, const float* __restrict__ beta,
    float* __restrict__ out)
{
    __shared__ float red[256];
    __shared__ float sh_mu, sh_rs;
    int tid = threadIdx.x;
    size_t base = (size_t)blockIdx.x * D_;

    float4 v = *(const float4*)&g_y[base + tid * 4];
    red[tid] = v.x + v.y + v.z + v.w;
    __syncthreads();
    for (int off = 128; off; off >>= 1) {
        if (tid < off) red[tid] += red[tid + off];
        __syncthreads();
    }
    if (tid == 0) sh_mu = red[0] * (1.0f / D_);
    __syncthreads();
    float mu = sh_mu;

    float d0 = v.x - mu, d1 = v.y - mu, d2 = v.z - mu, d3 = v.w - mu;
    red[tid] = d0 * d0 + d1 * d1 + d2 * d2 + d3 * d3;
    __syncthreads();
    for (int off = 128; off; off >>= 1) {
        if (tid < off) red[tid] += red[tid + off];
        __syncthreads();
    }
    if (tid == 0) sh_rs = rsqrtf(red[0] * (1.0f / D_) + 1e-5f);
    __syncthreads();
    float rs = sh_rs;

    int n = tid * 4;
    float4 g = *(const float4*)&gamma[n];
    float4 bt = *(const float4*)&beta[n];
    *(float4*)&out[base + n] = make_float4(d0 * rs * g.x + bt.x,
                                           d1 * rs * g.y + bt.y,
                                           d2 * rs * g.z + bt.z,
                                           d3 * rs * g.w + bt.w);
}

// ---------------------------------------------------------------------------
extern "C" void kernel_launch(void* const* d_in, const int* in_sizes, int n_in,
                              void* d_out, int out_size)
{
    const float* x     = (const float*)d_in[0];
    const float* mask  = (const float*)d_in[1];
    const float* Wq    = (const float*)d_in[2];
    const float* bq    = (const float*)d_in[3];
    const float* Wk    = (const float*)d_in[4];
    const float* bk    = (const float*)d_in[5];
    const float* Wv    = (const float*)d_in[6];
    const float* bv    = (const float*)d_in[7];
    const float* Wo    = (const float*)d_in[8];
    const float* bo    = (const float*)d_in[9];
    const float* gamma = (const float*)d_in[10];
    const float* beta  = (const float*)d_in[11];
    const float* cw    = (const float*)d_in[12];
    float* out = (float*)d_out;

    cudaFuncSetAttribute(attn_kernel,
                         cudaFuncAttributeMaxDynamicSharedMemorySize, ATTN_SMEM3);
    cudaFuncSetAttribute(qkv_mma_kernel,
                         cudaFuncAttributeMaxDynamicSharedMemorySize, GEMM_SMEM);
    cudaFuncSetAttribute(out_mma_kernel,
                         cudaFuncAttributeMaxDynamicSharedMemorySize, GEMM_SMEM);

    __nv_bfloat16 *xc, *wqc, *wkc, *wvc, *woc;
    cudaGetSymbolAddress((void**)&xc,  g_xc);
    cudaGetSymbolAddress((void**)&wqc, g_wqc);
    cudaGetSymbolAddress((void**)&wkc, g_wkc);
    cudaGetSymbolAddress((void**)&wvc, g_wvc);
    cudaGetSymbolAddress((void**)&woc, g_woc);

    conv_kernel<<<dim3(4096, 5), 256>>>(x, Wq, Wk, Wv, Wo, xc, wqc, wkc, wvc, woc);
    rope_tab_kernel<<<S_, HD_>>>();

    qkv_mma_kernel<<<dim3(D_ / 128, M_ / 128, 3), 256, GEMM_SMEM>>>(bq, bk, bv);

    attn_kernel<<<dim3(H_, BB_ * (S_ / 128)), 256, ATTN_SMEM3>>>(mask, cw);

    out_mma_kernel<<<dim3(D_ / 128, M_ / 128), 256, GEMM_SMEM>>>(x, bo);

    ln_kernel<<<M_, 256>>>(gamma, beta, out);
}

// round 16
// speedup vs baseline: 1.6460x; 1.6460x over previous
#include <cuda_runtime.h>
#include <cuda_bf16.h>
#include <math.h>
#include <stdint.h>

#define BB_ 2
#define S_  2048
#define D_  1024
#define H_  16
#define HD_ 64
#define M_  (BB_*S_)     // 4096
#define KTOT (2*D_)      // 2048 (hi|lo concatenated K)

// ---------------------------------------------------------------------------
// Scratch (device globals; no allocation allowed)
// ---------------------------------------------------------------------------
__device__ float g_y[M_*D_];
__device__ __nv_bfloat16 g_xc[M_*KTOT];       // x  hi|lo concat along K
__device__ __nv_bfloat16 g_wqc[D_*KTOT];
__device__ __nv_bfloat16 g_wkc[D_*KTOT];
__device__ __nv_bfloat16 g_wvc[D_*KTOT];
__device__ __nv_bfloat16 g_woc[D_*KTOT];
__device__ __nv_bfloat16 g_attnc[M_*KTOT];    // attention out hi|lo concat
__device__ __nv_bfloat16 g_qc[BB_*H_*S_*64];  // per-head Q bf16 (hi only)
__device__ __nv_bfloat16 g_kc[BB_*H_*S_*64];  // per-head K bf16 (hi only)
__device__ __nv_bfloat16 g_vc[BB_*H_*S_*128]; // per-head V bf16 [hi64|lo64]
__device__ float g_cos[S_*HD_];
__device__ float g_sin[S_*HD_];

// ---------------------------------------------------------------------------
// Helpers
// ---------------------------------------------------------------------------
__device__ __forceinline__ uint32_t smem_u32(const void* p) {
    uint32_t a;
    asm("{ .reg .u64 t; cvta.to.shared.u64 t, %1; cvt.u32.u64 %0, t; }" : "=r"(a) : "l"(p));
    return a;
}
__device__ __forceinline__ void cp16(uint32_t s, const void* g) {
    asm volatile("cp.async.cg.shared.global [%0], [%1], 16;" :: "r"(s), "l"(g));
}
__device__ __forceinline__ void ldsm4(uint32_t* r, uint32_t a) {
    asm volatile("ldmatrix.sync.aligned.m8n8.x4.shared.b16 {%0,%1,%2,%3}, [%4];"
                 : "=r"(r[0]), "=r"(r[1]), "=r"(r[2]), "=r"(r[3]) : "r"(a));
}
__device__ __forceinline__ void ldsm4t(uint32_t* r, uint32_t a) {
    asm volatile("ldmatrix.sync.aligned.m8n8.x4.trans.shared.b16 {%0,%1,%2,%3}, [%4];"
                 : "=r"(r[0]), "=r"(r[1]), "=r"(r[2]), "=r"(r[3]) : "r"(a));
}
__device__ __forceinline__ void ldsm2(uint32_t* r, uint32_t a) {
    asm volatile("ldmatrix.sync.aligned.m8n8.x2.shared.b16 {%0,%1}, [%2];"
                 : "=r"(r[0]), "=r"(r[1]) : "r"(a));
}
__device__ __forceinline__ void mma16816(float* c, const uint32_t* a, const uint32_t* b) {
    asm volatile("mma.sync.aligned.m16n8k16.row.col.f32.bf16.bf16.f32 "
                 "{%0,%1,%2,%3}, {%4,%5,%6,%7}, {%8,%9}, {%0,%1,%2,%3};"
                 : "+f"(c[0]), "+f"(c[1]), "+f"(c[2]), "+f"(c[3])
                 : "r"(a[0]), "r"(a[1]), "r"(a[2]), "r"(a[3]), "r"(b[0]), "r"(b[1]));
}
#define CP_COMMIT() asm volatile("cp.async.commit_group;" ::: "memory")
#define CP_WAIT(n)  asm volatile("cp.async.wait_group %0;" :: "n"(n) : "memory")

// pack two fp32 into bf16x2 hi (rounded) and lo (residual) words
__device__ __forceinline__ void split2(float v0, float v1, uint32_t& hi, uint32_t& lo) {
    __nv_bfloat16 h0 = __float2bfloat16(v0), h1 = __float2bfloat16(v1);
    float l0 = v0 - __bfloat162float(h0), l1 = v1 - __bfloat162float(h1);
    __nv_bfloat162 hp(h0, h1);
    __nv_bfloat162 lp(__float2bfloat16(l0), __float2bfloat16(l1));
    hi = *reinterpret_cast<uint32_t*>(&hp);
    lo = *reinterpret_cast<uint32_t*>(&lp);
}
__device__ __forceinline__ uint32_t packbf(float v0, float v1) {
    __nv_bfloat162 hp(__float2bfloat16(v0), __float2bfloat16(v1));
    return *reinterpret_cast<uint32_t*>(&hp);
}

// ---------------------------------------------------------------------------
// K0a: fp32 [R][1024] -> bf16 hi|lo concat [R][2048]; 5 tensors in one launch
// grid (4096, 5): y=0 -> x (4096 blocks), y=1..4 -> weights (1024 blocks each)
// ---------------------------------------------------------------------------
__global__ void __launch_bounds__(256) conv_kernel(
    const float* __restrict__ x, const float* __restrict__ wq,
    const float* __restrict__ wk, const float* __restrict__ wv,
    const float* __restrict__ wo,
    __nv_bfloat16* __restrict__ xc, __nv_bfloat16* __restrict__ wqc,
    __nv_bfloat16* __restrict__ wkc, __nv_bfloat16* __restrict__ wvc,
    __nv_bfloat16* __restrict__ woc)
{
    const float* src;
    __nv_bfloat16* dst;
    int z = blockIdx.y;
    if (z == 0)      { src = x;  dst = xc; }
    else if (z == 1) { src = wq; dst = wqc; if (blockIdx.x >= 1024) return; }
    else if (z == 2) { src = wk; dst = wkc; if (blockIdx.x >= 1024) return; }
    else if (z == 3) { src = wv; dst = wvc; if (blockIdx.x >= 1024) return; }
    else             { src = wo; dst = woc; if (blockIdx.x >= 1024) return; }

    size_t i = ((size_t)blockIdx.x * 256 + threadIdx.x) * 4;
    size_t r = i >> 10, c = i & 1023;
    float4 v = *(const float4*)(src + i);
    uint32_t h01, l01, h23, l23;
    split2(v.x, v.y, h01, l01);
    split2(v.z, v.w, h23, l23);
    size_t hb = r * KTOT + c;
    *(uint32_t*)(&dst[hb])            = h01;
    *(uint32_t*)(&dst[hb + 2])        = h23;
    *(uint32_t*)(&dst[hb + 1024])     = l01;
    *(uint32_t*)(&dst[hb + 1024 + 2]) = l23;
}

// ---------------------------------------------------------------------------
// K0b: RoPE sin/cos table
// ---------------------------------------------------------------------------
__global__ void rope_tab_kernel() {
    int s = blockIdx.x, hd = threadIdx.x;
    const float NLOG = 0.28782313662425574f; // ln(10000)/32
    float th = (float)s * expf(-(float)(hd & 31) * NLOG);
    float sv, cv;
    sincosf(th, &sv, &cv);
    g_cos[s * HD_ + hd] = cv;
    g_sin[s * HD_ + hd] = sv;
}

// ---------------------------------------------------------------------------
// mma.sync GEMM core: C[128,128] = A[128,2048] @ B[128,2048]^T (bf16, f32 acc)
// 4-stage cp.async pipeline, 3 loads in flight, one __syncthreads per K-iter.
// ---------------------------------------------------------------------------
#define BKg 32
#define NKIT (KTOT / BKg)  // 64
#define ASTRIDE 40
#define OPBYTES (128 * ASTRIDE * 2)   // 10240
#define GSTG (2 * OPBYTES)            // 20480 per stage (A+B)
#define GEMM_SMEM (4 * GSTG)          // 81920

__device__ __forceinline__ void gemm_loop(
    const __nv_bfloat16* __restrict__ Ab, const __nv_bfloat16* __restrict__ Bb,
    uint32_t base, float acc[4][4][4])
{
    int tid = threadIdx.x, lane = tid & 31, wid = tid >> 5;
    int wm = (wid >> 2) * 64, wn = (wid & 3) * 32;

    int r_ld = tid >> 1;
    int c_ld = (tid & 1) * 2;

    auto ldst = [&](int st, int k0) {
        uint32_t sA = base + (uint32_t)st * GSTG;
        uint32_t sB = sA + OPBYTES;
        #pragma unroll
        for (int j = 0; j < 2; j++) {
            int c = c_ld + j;
            uint32_t so = (uint32_t)(r_ld * 80 + c * 16);
            cp16(sA + so, Ab + (size_t)r_ld * KTOT + k0 + c * 8);
            cp16(sB + so, Bb + (size_t)r_ld * KTOT + k0 + c * 8);
        }
    };

    ldst(0, 0);        CP_COMMIT();
    ldst(1, BKg);      CP_COMMIT();
    ldst(2, 2 * BKg);  CP_COMMIT();

    int la = lane & 15, lka = (lane >> 4) << 3;
    int lb = lane & 7,  lkb = ((lane >> 3) & 1) << 3;

    for (int kt = 0; kt < NKIT; kt++) {
        CP_WAIT(2);
        __syncthreads();
        if (kt + 3 < NKIT) ldst((kt + 3) & 3, (kt + 3) * BKg);
        CP_COMMIT();

        int st = kt & 3;
        uint32_t aB = base + (uint32_t)st * GSTG;
        uint32_t bB = aB + OPBYTES;

        #pragma unroll
        for (int ks = 0; ks < 2; ks++) {
            int kk = ks * 16;
            uint32_t afr[4][4], bfr[4][2];
            #pragma unroll
            for (int mi = 0; mi < 4; mi++)
                ldsm4(afr[mi], aB + (uint32_t)(((wm + mi * 16 + la) * ASTRIDE + kk + lka) * 2));
            #pragma unroll
            for (int ni = 0; ni < 4; ni++)
                ldsm2(bfr[ni], bB + (uint32_t)(((wn + ni * 8 + lb) * ASTRIDE + kk + lkb) * 2));
            #pragma unroll
            for (int mi = 0; mi < 4; mi++)
                #pragma unroll
                for (int ni = 0; ni < 4; ni++)
                    mma16816(acc[mi][ni], afr[mi], bfr[ni]);
        }
    }
}

// ---------------------------------------------------------------------------
// K1: QKV projection (fused bias + RoPE), writes per-head bf16 layouts.
// grid (8, 32, 3), block 256.
// ---------------------------------------------------------------------------
__global__ void __launch_bounds__(256, 2) qkv_mma_kernel(
    const float* __restrict__ bq, const float* __restrict__ bk,
    const float* __restrict__ bv)
{
    extern __shared__ __align__(16) char gsm[];

    const __nv_bfloat16* Wc;
    const float* bias;
    __nv_bfloat16* outc;
    int dorope, isv;
    if (blockIdx.z == 0)      { Wc = g_wqc; bias = bq; outc = g_qc; dorope = 1; isv = 0; }
    else if (blockIdx.z == 1) { Wc = g_wkc; bias = bk; outc = g_kc; dorope = 1; isv = 0; }
    else                      { Wc = g_wvc; bias = bv; outc = g_vc; dorope = 0; isv = 1; }

    int m0 = blockIdx.y * 128, n0 = blockIdx.x * 128;
    float acc[4][4][4] = {};
    gemm_loop(g_xc + (size_t)m0 * KTOT, Wc + (size_t)n0 * KTOT, smem_u32(gsm), acc);

    int lane = threadIdx.x & 31, wid = threadIdx.x >> 5;
    int wm = (wid >> 2) * 64, wn = (wid & 3) * 32;

    #pragma unroll
    for (int mi = 0; mi < 4; mi++) {
        #pragma unroll
        for (int ni = 0; ni < 4; ni++) {
            int cc0 = n0 + wn + ni * 8 + (lane & 3) * 2;
            int h = cc0 >> 6, hd0 = cc0 & 63;
            float2 bi = *(const float2*)&bias[cc0];
            #pragma unroll
            for (int rr = 0; rr < 2; rr++) {
                int r = m0 + wm + mi * 16 + (lane >> 2) + rr * 8;
                int bb = r >> 11, s = r & (S_ - 1);
                float v0 = acc[mi][ni][rr * 2 + 0] + bi.x;
                float v1 = acc[mi][ni][rr * 2 + 1] + bi.y;
                if (dorope) {
                    float2 cs = *(const float2*)&g_cos[s * HD_ + hd0];
                    float2 sn = *(const float2*)&g_sin[s * HD_ + hd0];
                    float t0 = v0 * cs.x - v1 * sn.x;
                    float t1 = v1 * cs.y + v0 * sn.y;
                    v0 = t0; v1 = t1;
                }
                if (isv) {
                    uint32_t hw, lw;
                    split2(v0, v1, hw, lw);
                    size_t rowb = ((size_t)(bb * H_ + h) * S_ + s) * 128 + hd0;
                    *(uint32_t*)&outc[rowb]      = hw;
                    *(uint32_t*)&outc[rowb + 64] = lw;
                } else {
                    size_t rowb = ((size_t)(bb * H_ + h) * S_ + s) * 64 + hd0;
                    *(uint32_t*)&outc[rowb] = packbf(v0, v1);
                }
            }
        }
    }
}

// ---------------------------------------------------------------------------
// K2: attention via mma.sync bf16. grid (16 heads, 32 (b,qblk)), block 256.
// Q/K bf16 hi-only; V hi|lo. k-tile processed in two 32-col halves to keep
// live registers under the 128-reg cap -> 2 CTAs/SM.
// ---------------------------------------------------------------------------
#define QPITCH 144
#define KPITCH 144
#define VPITCH 272
#define QBYTES (128 * QPITCH)           // 18432
#define KSTG (64 * KPITCH)              // 9216
#define VSTG (64 * VPITCH)              // 17408
#define ASTG (KSTG + VSTG)              // 26624
#define ATTN_SMEM3 (QBYTES + 3 * ASTG)  // 98304

__global__ void __launch_bounds__(256, 2) attn_kernel(
    const float* __restrict__ mask, const float* __restrict__ cwp)
{
    extern __shared__ __align__(16) char smc[];
    uint32_t sb = smem_u32(smc);
    int tid = threadIdx.x, lane = tid & 31, wid = tid >> 5;
    int h = blockIdx.x;
    int b = blockIdx.y >> 4, qb = blockIdx.y & 15;
    int bh = b * H_ + h;
    int q0 = qb * 128;
    const __nv_bfloat16* Qg = g_qc + ((size_t)bh * S_ + q0) * 64;
    const __nv_bfloat16* Kg = g_kc + (size_t)bh * S_ * 64;
    const __nv_bfloat16* Vg = g_vc + (size_t)bh * S_ * 128;
    float cw = *cwp;
    const float* maskb = mask + (size_t)b * S_ * S_;

    auto stage_load = [&](int st, int kt2) {
        uint32_t kb = sb + (uint32_t)QBYTES + (uint32_t)st * ASTG;
        const __nv_bfloat16* Kp = Kg + (size_t)kt2 * 64 * 64;
        const __nv_bfloat16* Vp = Vg + (size_t)kt2 * 64 * 128;
        for (int i = tid; i < 512; i += 256) {
            int r = i >> 3, c = i & 7;
            cp16(kb + (uint32_t)(r * KPITCH + c * 16), Kp + (size_t)r * 64 + c * 8);
        }
        for (int i = tid; i < 1024; i += 256) {
            int r = i >> 4, c = i & 15;
            cp16(kb + (uint32_t)(KSTG + r * VPITCH + c * 16), Vp + (size_t)r * 128 + c * 8);
        }
    };

    // prologue: Q + stage0 in group 0; stage1 in group 1
    for (int i = tid; i < 1024; i += 256) {
        int r = i >> 3, c = i & 7;
        cp16(sb + (uint32_t)(r * QPITCH + c * 16), Qg + (size_t)r * 64 + c * 8);
    }
    stage_load(0, 0);
    CP_COMMIT();
    stage_load(1, 1);
    CP_COMMIT();

    uint32_t aQ[4][4];
    float oacc[8][4];
    #pragma unroll
    for (int n = 0; n < 8; n++)
        oacc[n][0] = oacc[n][1] = oacc[n][2] = oacc[n][3] = 0.f;
    float ls0 = 0.f, ls1 = 0.f;
    int r0q = q0 + wid * 16 + (lane >> 2);

    for (int kt = 0; kt < 32; kt++) {
        CP_WAIT(1);
        __syncthreads();
        if (kt == 0) {
            uint32_t qa = sb + (uint32_t)((wid * 16 + (lane & 15)) * QPITCH + ((lane >> 4) << 4));
            #pragma unroll
            for (int j = 0; j < 4; j++) ldsm4(aQ[j], qa + j * 32);
        }
        if (kt + 2 < 32) stage_load((kt + 2) % 3, kt + 2);
        CP_COMMIT();

        uint32_t Kb = sb + (uint32_t)QBYTES + (uint32_t)((kt % 3) * ASTG);
        uint32_t Vb = Kb + KSTG;

        uint32_t kbase = Kb + (uint32_t)((((lane & 7) + ((lane >> 4) & 1) * 8) * KPITCH)
                                         + ((lane >> 3) & 1) * 16);
        uint32_t vbase = Vb + (uint32_t)((((lane & 7) + ((lane >> 3) & 1) * 8) * VPITCH)
                                         + ((lane >> 4) & 1) * 16);

        // process this 64-col k-tile in two 32-col halves (register pressure)
        #pragma unroll
        for (int half = 0; half < 2; half++) {
            // ---- QK^T over hd=64 (bf16 hi): np in {2*half, 2*half+1}
            float sc[4][4];
            #pragma unroll
            for (int n = 0; n < 4; n++)
                sc[n][0] = sc[n][1] = sc[n][2] = sc[n][3] = 0.f;

            #pragma unroll
            for (int j = 0; j < 4; j++) {
                #pragma unroll
                for (int npl = 0; npl < 2; npl++) {
                    int np = half * 2 + npl;
                    uint32_t bf[4];
                    ldsm4(bf, kbase + (uint32_t)(np * (16 * KPITCH) + j * 32));
                    mma16816(sc[2 * npl],     aQ[j], bf);
                    mma16816(sc[2 * npl + 1], aQ[j], bf + 2);
                }
            }

            // ---- softmax (shift=0): p = exp(s/8 + mask*cw) -> bf16 P frags
            uint32_t Pa[4], Pb[4];
            {
                int kcol0 = kt * 64 + half * 32 + (lane & 3) * 2;
                const float* mrow0 = maskb + (size_t)r0q * S_ + kcol0;
                const float* mrow1 = mrow0 + 8 * S_;
                #pragma unroll
                for (int nl = 0; nl < 4; nl++) {
                    float2 m0 = *(const float2*)(mrow0 + nl * 8);
                    float2 m1 = *(const float2*)(mrow1 + nl * 8);
                    float p0 = __expf(fmaf(m0.x, cw, sc[nl][0] * 0.125f));
                    float p1 = __expf(fmaf(m0.y, cw, sc[nl][1] * 0.125f));
                    float p2 = __expf(fmaf(m1.x, cw, sc[nl][2] * 0.125f));
                    float p3 = __expf(fmaf(m1.y, cw, sc[nl][3] * 0.125f));
                    ls0 += p0 + p1; ls1 += p2 + p3;
                    Pa[nl] = packbf(p0, p1);
                    Pb[nl] = packbf(p2, p3);
                }
            }

            // ---- P @ V: [Phi|Phi] x [Vhi|Vlo]; js in {2*half, 2*half+1}
            #pragma unroll
            for (int jsl = 0; jsl < 2; jsl++) {
                int js = half * 2 + jsl;
                uint32_t aPf[4] = {Pa[2 * jsl], Pb[2 * jsl],
                                   Pa[2 * jsl + 1], Pb[2 * jsl + 1]};
                #pragma unroll
                for (int nh = 0; nh < 4; nh++) {
                    uint32_t vf[4];
                    ldsm4t(vf, vbase + (uint32_t)(js * (16 * VPITCH) + nh * 32));
                    mma16816(oacc[2 * nh],     aPf, vf);
                    mma16816(oacc[2 * nh + 1], aPf, vf + 2);
                    uint32_t vl[4];
                    ldsm4t(vl, vbase + (uint32_t)(js * (16 * VPITCH) + nh * 32 + 128));
                    mma16816(oacc[2 * nh],     aPf, vl);
                    mma16816(oacc[2 * nh + 1], aPf, vl + 2);
                }
            }
        }
    }

    // ---- epilogue: row sums, normalize, write bf16 hi|lo concat
    ls0 += __shfl_xor_sync(0xffffffffu, ls0, 1);
    ls0 += __shfl_xor_sync(0xffffffffu, ls0, 2);
    ls1 += __shfl_xor_sync(0xffffffffu, ls1, 1);
    ls1 += __shfl_xor_sync(0xffffffffu, ls1, 2);
    float inv0 = 1.0f / ls0, inv1 = 1.0f / ls1;

    size_t row0 = (size_t)(b * S_ + r0q) * KTOT;
    size_t row1 = row0 + (size_t)8 * KTOT;
    int colh = h * 64 + (lane & 3) * 2;
    #pragma unroll
    for (int n = 0; n < 8; n++) {
        int cc = colh + n * 8;
        uint32_t h0w, l0w, h1w, l1w;
        split2(oacc[n][0] * inv0, oacc[n][1] * inv0, h0w, l0w);
        split2(oacc[n][2] * inv1, oacc[n][3] * inv1, h1w, l1w);
        *(uint32_t*)&g_attnc[row0 + cc]        = h0w;
        *(uint32_t*)&g_attnc[row0 + 1024 + cc] = l0w;
        *(uint32_t*)&g_attnc[row1 + cc]        = h1w;
        *(uint32_t*)&g_attnc[row1 + 1024 + cc] = l1w;
    }
}

// ---------------------------------------------------------------------------
// K3: output projection + bias + residual. grid (8, 32), block 256.
// ---------------------------------------------------------------------------
__global__ void __launch_bounds__(256, 2) out_mma_kernel(
    const float* __restrict__ x, const float* __restrict__ bo)
{
    extern __shared__ __align__(16) char gsm[];

    int m0 = blockIdx.y * 128, n0 = blockIdx.x * 128;
    float acc[4][4][4] = {};
    gemm_loop(g_attnc + (size_t)m0 * KTOT, g_woc + (size_t)n0 * KTOT, smem_u32(gsm), acc);

    int lane = threadIdx.x & 31, wid = threadIdx.x >> 5;
    int wm = (wid >> 2) * 64, wn = (wid & 3) * 32;

    #pragma unroll
    for (int mi = 0; mi < 4; mi++) {
        #pragma unroll
        for (int ni = 0; ni < 4; ni++) {
            int cc0 = n0 + wn + ni * 8 + (lane & 3) * 2;
            float2 bi = *(const float2*)&bo[cc0];
            #pragma unroll
            for (int rr = 0; rr < 2; rr++) {
                int r = m0 + wm + mi * 16 + (lane >> 2) + rr * 8;
                float2 xr = *(const float2*)&x[(size_t)r * D_ + cc0];
                *(float2*)&g_y[(size_t)r * D_ + cc0] =
                    make_float2(acc[mi][ni][rr * 2 + 0] + bi.x + xr.x,
                                acc[mi][ni][rr * 2 + 1] + bi.y + xr.y);
            }
        }
    }
}

// ---------------------------------------------------------------------------
// K4: LayerNorm over last dim. grid 4096, block 256.
// ---------------------------------------------------------------------------
__global__ void __launch_bounds__(256) ln_kernel(
    const float* __restrict__ gamma, const float* __restrict__ beta,
    float* __restrict__ out)
{
    __shared__ float red[256];
    __shared__ float sh_mu, sh_rs;
    int tid = threadIdx.x;
    size_t base = (size_t)blockIdx.x * D_;

    float4 v = *(const float4*)&g_y[base + tid * 4];
    red[tid] = v.x + v.y + v.z + v.w;
    __syncthreads();
    for (int off = 128; off; off >>= 1) {
        if (tid < off) red[tid] += red[tid + off];
        __syncthreads();
    }
    if (tid == 0) sh_mu = red[0] * (1.0f / D_);
    __syncthreads();
    float mu = sh_mu;

    float d0 = v.x - mu, d1 = v.y - mu, d2 = v.z - mu, d3 = v.w - mu;
    red[tid] = d0 * d0 + d1 * d1 + d2 * d2 + d3 * d3;
    __syncthreads();
    for (int off = 128; off; off >>= 1) {
        if (tid < off) red[tid] += red[tid + off];
        __syncthreads();
    }
    if (tid == 0) sh_rs = rsqrtf(red[0] * (1.0f / D_) + 1e-5f);
    __syncthreads();
    float rs = sh_rs;

    int n = tid * 4;
    float4 g = *(const float4*)&gamma[n];
    float4 bt = *(const float4*)&beta[n];
    *(float4*)&out[base + n] = make_float4(d0 * rs * g.x + bt.x,
                                           d1 * rs * g.y + bt.y,
                                           d2 * rs * g.z + bt.z,
                                           d3 * rs * g.w + bt.w);
}

// ---------------------------------------------------------------------------
extern "C" void kernel_launch(void* const* d_in, const int* in_sizes, int n_in,
                              void* d_out, int out_size)
{
    const float* x     = (const float*)d_in[0];
    const float* mask  = (const float*)d_in[1];
    const float* Wq    = (const float*)d_in[2];
    const float* bq    = (const float*)d_in[3];
    const float* Wk    = (const float*)d_in[4];
    const float* bk    = (const float*)d_in[5];
    const float* Wv    = (const float*)d_in[6];
    const float* bv    = (const float*)d_in[7];
    const float* Wo    = (const float*)d_in[8];
    const float* bo    = (const float*)d_in[9];
    const float* gamma = (const float*)d_in[10];
    const float* beta  = (const float*)d_in[11];
    const float* cw    = (const float*)d_in[12];
    float* out = (float*)d_out;

    cudaFuncSetAttribute(attn_kernel,
                         cudaFuncAttributeMaxDynamicSharedMemorySize, ATTN_SMEM3);
    cudaFuncSetAttribute(qkv_mma_kernel,
                         cudaFuncAttributeMaxDynamicSharedMemorySize, GEMM_SMEM);
    cudaFuncSetAttribute(out_mma_kernel,
                         cudaFuncAttributeMaxDynamicSharedMemorySize, GEMM_SMEM);

    __nv_bfloat16 *xc, *wqc, *wkc, *wvc, *woc;
    cudaGetSymbolAddress((void**)&xc,  g_xc);
    cudaGetSymbolAddress((void**)&wqc, g_wqc);
    cudaGetSymbolAddress((void**)&wkc, g_wkc);
    cudaGetSymbolAddress((void**)&wvc, g_wvc);
    cudaGetSymbolAddress((void**)&woc, g_woc);

    conv_kernel<<<dim3(4096, 5), 256>>>(x, Wq, Wk, Wv, Wo, xc, wqc, wkc, wvc, woc);
    rope_tab_kernel<<<S_, HD_>>>();

    qkv_mma_kernel<<<dim3(D_ / 128, M_ / 128, 3), 256, GEMM_SMEM>>>(bq, bk, bv);

    attn_kernel<<<dim3(H_, BB_ * (S_ / 128)), 256, ATTN_SMEM3>>>(mask, cw);

    out_mma_kernel<<<dim3(D_ / 128, M_ / 128), 256, GEMM_SMEM>>>(x, bo);

    ln_kernel<<<M_, 256>>>(gamma, beta, out);
}